// round 12
// baseline (speedup 1.0000x reference)
#include <cuda_runtime.h>
#include <cstdint>

// Quantum autoencoder forward, batch=256. R12 = R11 math + grid shaping:
// 2 samples per 256-thread CTA -> grid=128 (single wave, <=1 CTA/SM, balanced),
// doubled per-SM warp count for latency cover; all LDGs front-loaded.
//
// R11 math (verified): X-eigenbasis diagonal simulation; embedding+gates are
// 50 signed terms ang(x) = -1/2 sum_t alpha_t (-1)^{parity(rho_t . x)}; a GF(2)
// basis transform puts all 7 correlation masks in the low 3 bits, so with 8
// elements/thread the swap-test sum telescopes:
//   P(aux=1) = 0.5 - 2^-14 * sum_threads ( (sum_e re_e)^2 + (sum_e im_e)^2 )

#define NUM_Q 10
#define DEPTH 4
#define BATCH 256
#define TPB 256
#define SPB 2              // samples per CTA
#define NGATES 40
#define NTERMS 50
#define FULLM 0xFFFFFFFFu

struct XForm {
    unsigned rho[NTERMS];   // transformed parity vectors (10 bits each)
};

__host__ __device__ constexpr int cpar(unsigned v) {
    int n = 0;
    while (v) { n ^= (int)(v & 1u); v >>= 1; }
    return n;
}

__host__ __device__ constexpr unsigned creduce(unsigned v, const unsigned* ech, int ne) {
    for (int i = 0; i < ne; ++i) {
        unsigned h = ech[i];
        unsigned m = 0x200u;
        while (m && !(h & m)) m >>= 1;
        if (v & m) v ^= h;
    }
    return v;
}

__host__ __device__ constexpr XForm make_xform() {
    // circuit Clifford tracking (identical to verified R6 code)
    unsigned lr[NUM_Q] = {}, kc[NUM_Q] = {};
    unsigned rg[NGATES] = {};                 // gate parity vectors, old basis
    for (int b = 0; b < NUM_Q; ++b) { lr[b] = 1u << b; kc[b] = 1u << b; }
    for (int l = 0; l < DEPTH; ++l) {
        for (int w = 0; w < NUM_Q; ++w) rg[l * NUM_Q + w] = lr[9 - w];
        for (int w = 0; w < NUM_Q; ++w) {
            const int cb = 9 - w;
            const int tb = (w < 9) ? (8 - w) : 9;
            lr[cb] ^= lr[tb];
            kc[tb] ^= kc[cb];
        }
    }
    // invcol = columns of T^{-1}: first the 3 measurement columns, then extend
    unsigned invcol[NUM_Q] = {};
    unsigned ech[NUM_Q] = {};
    int ne = 0;
    for (int c = 0; c < 3; ++c) {
        invcol[c] = kc[c];
        ech[ne++] = creduce(kc[c], ech, ne);
    }
    int cnt = 3;
    for (int b = 0; b < NUM_Q && cnt < NUM_Q; ++b) {
        const unsigned v = 1u << b;
        const unsigned r = creduce(v, ech, ne);
        if (r) { invcol[cnt++] = v; ech[ne++] = r; }
    }
    // transformed parity vectors: rho'_j = parity(rho_old & invcol[j])
    XForm X{};
    for (int t = 0; t < NTERMS; ++t) {
        const unsigned old = (t < NUM_Q) ? (1u << t) : rg[t - NUM_Q];
        unsigned v = 0;
        for (int j = 0; j < NUM_Q; ++j)
            v |= (unsigned)cpar(old & invcol[j]) << j;
        X.rho[t] = v;
    }
    return X;
}

constexpr XForm TX = make_xform();

// per-tid7 hi-sign table: bit t = parity((rho[t]>>3) & tid7)
struct PTab { unsigned long long p[128]; };

__host__ __device__ constexpr PTab make_ptab() {
    PTab t{};
    for (unsigned tid = 0; tid < 128; ++tid) {
        unsigned long long v = 0;
        for (int g = 0; g < NTERMS; ++g)
            v |= (unsigned long long)(unsigned)cpar((TX.rho[g] >> 3) & tid) << g;
        t.p[tid] = v;
    }
    return t;
}

__device__ const PTab d_ptab = make_ptab();

// ---- 50 signed terms into 8 group accumulators ----
template<int T>
__device__ __forceinline__ void terms(float (&C)[8], const float (&fw)[NUM_Q],
                                      const float (&th)[NGATES],
                                      unsigned plo, unsigned phi) {
    if constexpr (T < NTERMS) {
        constexpr int m = (int)(TX.rho[T] & 7u);
        float alpha;
        if constexpr (T < NUM_Q) alpha = fw[9 - T];   // embed term for bit T
        else                     alpha = th[T - NUM_Q];
        unsigned sgn;
        if constexpr (T < 32) sgn = (plo << (31 - T)) & 0x80000000u;
        else                  sgn = (phi << (63 - T)) & 0x80000000u;
        C[m] += __uint_as_float(__float_as_uint(alpha) ^ sgn);
        terms<T + 1>(C, fw, th, plo, phi);
    }
}

__global__ void __launch_bounds__(TPB, 1)
qae_kernel(const float* __restrict__ features,
           const float* __restrict__ weights,
           float* __restrict__ out)
{
    __shared__ float s_wsum[TPB / 32];

    const int tid = threadIdx.x;
    const int tid7 = tid & 127;                      // hi 7 bits of x'
    const int samp = blockIdx.x * SPB + (tid >> 7);  // sample for this half-CTA
    const float* f = features + samp * NUM_Q;

    // ---- front-load ALL memory ops so their latencies overlap ----
    const unsigned long long pm = d_ptab.p[tid7];    // 1KB table, L2-hot

    float fw[NUM_Q];
#pragma unroll
    for (int q = 0; q < NUM_Q / 2; ++q) {            // row stride 40B -> 8B aligned
        const float2 v = __ldg(reinterpret_cast<const float2*>(f) + q);
        fw[2 * q] = v.x; fw[2 * q + 1] = v.y;
    }
    float th[NGATES];
#pragma unroll
    for (int q = 0; q < NGATES / 4; ++q) {
        const float4 v = __ldg(reinterpret_cast<const float4*>(weights) + q);
        th[4 * q + 0] = v.x; th[4 * q + 1] = v.y;
        th[4 * q + 2] = v.z; th[4 * q + 3] = v.w;
    }

    const unsigned plo = (unsigned)pm;
    const unsigned phi = (unsigned)(pm >> 32);

    // 50 signed terms -> 8 group sums
    float C[8] = {0.0f, 0.0f, 0.0f, 0.0f, 0.0f, 0.0f, 0.0f, 0.0f};
    terms<0>(C, fw, th, plo, phi);

    // 3-stage Walsh-Hadamard: ang[e] = -0.5 * sum_m (-1)^{popc(m&e)} C[m]
#pragma unroll
    for (int bit = 1; bit < 8; bit <<= 1) {
#pragma unroll
        for (int i = 0; i < 8; ++i) {
            if (!(i & bit)) {
                const float a = C[i], b = C[i | bit];
                C[i] = a + b;
                C[i | bit] = a - b;
            }
        }
    }

    // 8 unit phasors; SR/SI tree sums
    float re[8], im[8];
#pragma unroll
    for (int e = 0; e < 8; ++e)
        __sincosf(-0.5f * C[e], &im[e], &re[e]);

    const float SR = ((re[0] + re[1]) + (re[2] + re[3]))
                   + ((re[4] + re[5]) + (re[6] + re[7]));
    const float SI = ((im[0] + im[1]) + (im[2] + im[3]))
                   + ((im[4] + im[5]) + (im[6] + im[7]));
    float q = fmaf(SR, SR, SI * SI);

    // segment-local reduction: warps 0-3 = sample A, warps 4-7 = sample B
#pragma unroll
    for (int off = 16; off; off >>= 1)
        q += __shfl_xor_sync(FULLM, q, off);
    if ((tid & 31) == 0) s_wsum[tid >> 5] = q;
    __syncthreads();
    if ((tid & 127) == 0) {
        const int w0 = (tid >> 5);                   // 0 or 4
        const float v = (s_wsum[w0] + s_wsum[w0 + 1])
                      + (s_wsum[w0 + 2] + s_wsum[w0 + 3]);
        out[samp] = 0.5f - v * 6.103515625e-05f;     // 2^-14
    }
}

extern "C" void kernel_launch(void* const* d_in, const int* in_sizes, int n_in,
                              void* d_out, int out_size)
{
    const float* features = (const float*)d_in[0];  // [256, 10]
    const float* weights  = (const float*)d_in[1];  // [4, 10]
    float* out = (float*)d_out;                     // [256]
    (void)in_sizes; (void)n_in; (void)out_size;

    qae_kernel<<<BATCH / SPB, TPB>>>(features, weights, out);
}